// round 1
// baseline (speedup 1.0000x reference)
#include <cuda_runtime.h>

// ---------------------------------------------------------------------------
// CharacterEmbeddingLayer: char-CNN (windows 2..5, 100 filters each, tanh +
// maxpool) -> 400 feats -> 400x128 projection -> 2 highway layers -> [.,128].
//
// Inputs (metadata order):
//  0 char_idxs   int32  [64,400,16]
//  1 char_vectors f32   [96,64]
//  2 filt2  f32 [100,128]   3 filt3 [100,192]   4 filt4 [100,256]  5 filt5 [100,320]
//  6 w_proj f32 [128,400]
//  7 t_w0 [128,128]  8 t_b0 [128]  9 t_w1 [128,128] 10 t_b1 [128]
// 11 g_w0 [128,128] 12 g_b0 [128] 13 g_w1 [128,128] 14 g_b1 [128]
// out f32 [64,400,128]
// ---------------------------------------------------------------------------

#define NTOK  25600      // 64*400 tokens
#define NF    100

typedef unsigned long long u64;

// scratch for conv outputs: [NTOK, 400] fp32 (~41 MB, device global = allowed)
__device__ float g_outs[(size_t)NTOK * 400];

// ---------------- packed fp32x2 helpers (sm_100+) ---------------------------
__device__ __forceinline__ void ffma2(u64 &acc, u64 a, u64 b) {
    asm("fma.rn.f32x2 %0, %1, %2, %0;" : "+l"(acc) : "l"(a), "l"(b));
}
__device__ __forceinline__ float hadd2(u64 v) {
    float lo, hi;
    asm("mov.b64 {%0, %1}, %2;" : "=f"(lo), "=f"(hi) : "l"(v));
    return lo + hi;
}
__device__ __forceinline__ float tanh_fast(float x) {
    float y;
    asm("tanh.approx.f32 %0, %1;" : "=f"(y) : "f"(x));
    return y;
}

// ---------------------------------------------------------------------------
// Kernel 1: conv branches.  8 tokens/CTA (1 token per warp), 256 threads.
// Dynamic smem: embed [8][16][64] f32  +  filter tile [32][W*64+4] f32 + idx.
// Inner loop: lane = filter, full-length dot in registers via FFMA2,
// embed reads are warp-broadcast LDS.128 (1 phase), filter reads LDS.128.
// ---------------------------------------------------------------------------
#define TPC      8
#define T1       256
#define ES_FLOATS (TPC * 16 * 64)            // 8192
#define FS_FLOATS (32 * (5 * 64 + 4))        // 10368 (sized for W=5 pitch)
#define SMEM1_BYTES ((ES_FLOATS + FS_FLOATS) * 4 + TPC * 16 * 4)

template<int W>
__device__ __forceinline__ float conv_dot(const float* __restrict__ es_tok,
                                          const float* __restrict__ frow)
{
    constexpr int L = 17 - W;      // valid window positions
    u64 acc[L];
    #pragma unroll
    for (int l = 0; l < L; l++) acc[l] = 0ull;

    #pragma unroll 1
    for (int d4 = 0; d4 < 16; d4++) {          // 4 fp32 (=2 f32x2) per step
        ulonglong2 fv[W];
        #pragma unroll
        for (int p = 0; p < W; p++)
            fv[p] = *reinterpret_cast<const ulonglong2*>(frow + p * 64 + 4 * d4);
        #pragma unroll
        for (int j = 0; j < 16; j++) {
            ulonglong2 ev = *reinterpret_cast<const ulonglong2*>(es_tok + j * 64 + 4 * d4);
            #pragma unroll
            for (int p = 0; p < W; p++) {
                const int l = j - p;           // folded at compile time
                if (l >= 0 && l < L) {
                    ffma2(acc[l], ev.x, fv[p].x);
                    ffma2(acc[l], ev.y, fv[p].y);
                }
            }
        }
    }
    float vm = -2.0f;                           // tanh in [-1,1]
    #pragma unroll
    for (int l = 0; l < L; l++)
        vm = fmaxf(vm, tanh_fast(hadd2(acc[l])));
    return vm;
}

template<int W>
__device__ __forceinline__ void run_branch(const float* __restrict__ filt,
                                           const float* es_all, float* fs,
                                           int tid, int lane, int warp,
                                           float* __restrict__ outrow)
{
    constexpr int KW    = W * 64;
    constexpr int PITCH = KW + 4;              // 16B-aligned rows, spread quad-banks
    for (int f0 = 0; f0 < NF; f0 += 32) {
        __syncthreads();                        // also orders es fill on 1st pass
        const int nf = (NF - f0 < 32) ? (NF - f0) : 32;
        for (int i = tid; i < nf * KW; i += T1) {
            const int fl = i / KW;
            const int k  = i - fl * KW;
            fs[fl * PITCH + k] = filt[(f0 + fl) * KW + k];
        }
        __syncthreads();
        const float vm = conv_dot<W>(es_all + warp * 1024, fs + lane * PITCH);
        if (f0 + lane < NF) outrow[f0 + lane] = vm;
    }
}

__global__ void __launch_bounds__(T1, 3)
conv_kernel(const int*   __restrict__ idxs,
            const float* __restrict__ cv,
            const float* __restrict__ f2, const float* __restrict__ f3,
            const float* __restrict__ f4, const float* __restrict__ f5)
{
    extern __shared__ char smem_raw[];
    float* es   = reinterpret_cast<float*>(smem_raw);
    float* fs   = es + ES_FLOATS;
    int*   sidx = reinterpret_cast<int*>(fs + FS_FLOATS);

    const int tid  = threadIdx.x;
    const int warp = tid >> 5;
    const int lane = tid & 31;
    const int tok0 = blockIdx.x * TPC;          // grid = 3200, exact
    const int token = tok0 + warp;

    if (tid < TPC * 16)
        sidx[tid] = idxs[(tok0 + (tid >> 4)) * 16 + (tid & 15)];
    __syncthreads();

    // gather: es[t][j][d] = char_vectors[idx][d]
    #pragma unroll 4
    for (int i = tid; i < ES_FLOATS; i += T1) {
        const int t = i >> 10, j = (i >> 6) & 15, d = i & 63;
        es[i] = cv[sidx[t * 16 + j] * 64 + d];
    }
    // (first __syncthreads inside run_branch orders the fill vs. compute)

    float* outrow = g_outs + (size_t)token * 400;
    run_branch<2>(f2, es, fs, tid, lane, warp, outrow + 0);
    run_branch<3>(f3, es, fs, tid, lane, warp, outrow + 100);
    run_branch<4>(f4, es, fs, tid, lane, warp, outrow + 200);
    run_branch<5>(f5, es, fs, tid, lane, warp, outrow + 300);
}

// ---------------------------------------------------------------------------
// Kernel 2: projection (400->128, no bias) + 2 highway layers.
// 8 tokens/CTA, 128 threads (thread = output channel).
// ---------------------------------------------------------------------------
__device__ __forceinline__ void highway_layer(const float* __restrict__ tw,
                                              const float* __restrict__ tb,
                                              const float* __restrict__ gw,
                                              const float* __restrict__ gb,
                                              float x[8], float (*sx)[128], int n)
{
    u64 at[8], ag[8];
    #pragma unroll
    for (int t = 0; t < 8; t++) { at[t] = 0ull; ag[t] = 0ull; }
    const float* trow = tw + n * 128;
    const float* grow = gw + n * 128;
    #pragma unroll 2
    for (int k2 = 0; k2 < 64; k2++) {
        const u64 tv = *reinterpret_cast<const u64*>(trow + 2 * k2);
        const u64 gv = *reinterpret_cast<const u64*>(grow + 2 * k2);
        #pragma unroll
        for (int t = 0; t < 8; t++) {
            const u64 xv = *reinterpret_cast<const u64*>(&sx[t][2 * k2]);
            ffma2(at[t], xv, tv);
            ffma2(ag[t], xv, gv);
        }
    }
    const float tbv = tb[n], gbv = gb[n];
    __syncthreads();                            // all reads of sx done
    #pragma unroll
    for (int t = 0; t < 8; t++) {
        const float tval = fmaxf(hadd2(at[t]) + tbv, 0.0f);
        const float z    = hadd2(ag[t]) + gbv;
        const float g    = 1.0f / (1.0f + __expf(-z));
        x[t] = g * tval + (1.0f - g) * x[t];
        sx[t][n] = x[t];
    }
    __syncthreads();                            // sx updated for next layer
}

__global__ void __launch_bounds__(128)
head_kernel(const float* __restrict__ wp,
            const float* __restrict__ tw0, const float* __restrict__ tb0,
            const float* __restrict__ tw1, const float* __restrict__ tb1,
            const float* __restrict__ gw0, const float* __restrict__ gb0,
            const float* __restrict__ gw1, const float* __restrict__ gb1,
            float* __restrict__ out)
{
    __shared__ float so[8][400];
    __shared__ float sx[8][128];
    const int n    = threadIdx.x;               // output channel
    const int tok0 = blockIdx.x * 8;

    const float* src = g_outs + (size_t)tok0 * 400;
    #pragma unroll 4
    for (int i = n; i < 8 * 400; i += 128)
        (&so[0][0])[i] = src[i];
    __syncthreads();

    // projection: x[n] = sum_k outs[k] * w_proj[n,k]
    u64 acc[8];
    #pragma unroll
    for (int t = 0; t < 8; t++) acc[t] = 0ull;
    const float* wrow = wp + n * 400;
    #pragma unroll 2
    for (int k2 = 0; k2 < 200; k2++) {
        const u64 wv = *reinterpret_cast<const u64*>(wrow + 2 * k2);
        #pragma unroll
        for (int t = 0; t < 8; t++) {
            const u64 xv = *reinterpret_cast<const u64*>(&so[t][2 * k2]);
            ffma2(acc[t], xv, wv);
        }
    }
    float x[8];
    #pragma unroll
    for (int t = 0; t < 8; t++) { x[t] = hadd2(acc[t]); sx[t][n] = x[t]; }
    __syncthreads();

    highway_layer(tw0, tb0, gw0, gb0, x, sx, n);
    highway_layer(tw1, tb1, gw1, gb1, x, sx, n);

    #pragma unroll
    for (int t = 0; t < 8; t++)
        out[(size_t)(tok0 + t) * 128 + n] = x[t];
}

// ---------------------------------------------------------------------------
extern "C" void kernel_launch(void* const* d_in, const int* in_sizes, int n_in,
                              void* d_out, int out_size)
{
    const int*   idxs = (const int*)  d_in[0];
    const float* cv   = (const float*)d_in[1];
    const float* f2   = (const float*)d_in[2];
    const float* f3   = (const float*)d_in[3];
    const float* f4   = (const float*)d_in[4];
    const float* f5   = (const float*)d_in[5];
    const float* wp   = (const float*)d_in[6];
    const float* tw0  = (const float*)d_in[7];
    const float* tb0  = (const float*)d_in[8];
    const float* tw1  = (const float*)d_in[9];
    const float* tb1  = (const float*)d_in[10];
    const float* gw0  = (const float*)d_in[11];
    const float* gb0  = (const float*)d_in[12];
    const float* gw1  = (const float*)d_in[13];
    const float* gb1  = (const float*)d_in[14];
    float* out = (float*)d_out;

    cudaFuncSetAttribute(conv_kernel,
                         cudaFuncAttributeMaxDynamicSharedMemorySize, SMEM1_BYTES);

    conv_kernel<<<NTOK / TPC, T1, SMEM1_BYTES>>>(idxs, cv, f2, f3, f4, f5);
    head_kernel<<<NTOK / 8, 128>>>(wp, tw0, tb0, tw1, tb1, gw0, gb0, gw1, gb1, out);
}